// round 9
// baseline (speedup 1.0000x reference)
#include <cuda_runtime.h>
#include <cuda_fp16.h>
#include <cstdint>

// ---------------- problem-size bounds (fixed by the dataset) ----------------
#define NMAX 20000
#define EMAX 320000
#define FIN  518
#define DH   128     // node embedding dim
#define HEADS 4
#define HD   512     // HEADS * DH
#define CAP  128     // cached edges per node (overflow recomputed)

// ---------------- device scratch (no allocations allowed) -------------------
__device__ float  g_xr[NMAX * FIN];       // x rounded to tf32 grid
__device__ float  g_wr[FIN * 256 + 256 * DH + 2 * DH * HD];  // rounded weights
__device__ float  g_hidden[NMAX * 256];   // encoder hidden (tf32 grid)
__device__ float  g_h0[NMAX * DH];        // encoder out (tf32 grid)
__device__ float  g_h1[NMAX * DH];        // layer1 out (tf32 grid)
__device__ __half g_hlinh[NMAX * HD];     // h @ lin in fp16, layout [n][L][head][4]
__device__ float  g_as[NMAX * HEADS];
__device__ float  g_ad[NMAX * HEADS];
__device__ int    g_cnt[NMAX];            // zero at load; re-zeroed by scan each call
__device__ int    g_cursor[NMAX];         // scatter cursors (scan initializes)
__device__ int    g_rowptr[NMAX + 1];
__device__ int2   g_cedge[EMAX];               // packed {src, type} per CSR slot
__device__ float  g_relproj[2 * 26 * HEADS];   // [layer][26][4]

__device__ __forceinline__ uint32_t f2tf32(float f) {
    uint32_t u;
    asm("cvt.rna.tf32.f32 %0, %1;" : "=r"(u) : "f"(f));
    return u;
}
__device__ __forceinline__ float rnd_tf32(float f) {
    return __uint_as_float(f2tf32(f));
}

// ---------------- hist + tf32 pre-rounding (fused) ---------------------------
__global__ void hist_round_kernel(const int* __restrict__ dst, int E,
                                  int* __restrict__ cnt,
                                  const float* __restrict__ x, float* __restrict__ xr, long nx,
                                  const float* __restrict__ w1, long nw1,
                                  const float* __restrict__ w2, long nw2,
                                  const float* __restrict__ l1, long nl,
                                  const float* __restrict__ l2,
                                  float* __restrict__ wr) {
    long gid = blockIdx.x * (long)blockDim.x + threadIdx.x;
    if (gid < E) atomicAdd(&cnt[dst[gid]], 1);
    const long stride = (long)gridDim.x * blockDim.x;
    const long total = nx + nw1 + nw2 + 2 * nl;
    for (long i = gid; i < total; i += stride) {
        if (i < nx) { xr[i] = rnd_tf32(x[i]); continue; }
        long j = i - nx;
        if (j < nw1)      { wr[j] = rnd_tf32(w1[j]); continue; }
        j -= nw1;
        if (j < nw2)      { wr[nw1 + j] = rnd_tf32(w2[j]); continue; }
        j -= nw2;
        if (j < nl)       { wr[nw1 + nw2 + j] = rnd_tf32(l1[j]); continue; }
        j -= nl;
        wr[nw1 + nw2 + nl + j] = rnd_tf32(l2[j]);
    }
}

// single-block exclusive scan of cnt[0..n) -> rowptr[0..n] and cursor[0..n).
// Also zeroes cnt (so the next invocation's hist starts from zero).
__global__ void scan_kernel(int* __restrict__ cnt, int* __restrict__ rowptr,
                            int* __restrict__ cursor, int n) {
    __shared__ int part[1024];
    int tid = threadIdx.x;
    int chunk = (n + 1023) / 1024;
    int b = tid * chunk;
    int e = min(b + chunk, n);
    int s = 0;
    for (int i = b; i < e; i++) { s += cnt[i]; }
    part[tid] = s;
    __syncthreads();
    for (int off = 1; off < 1024; off <<= 1) {
        int v = (tid >= off) ? part[tid - off] : 0;
        __syncthreads();
        part[tid] += v;
        __syncthreads();
    }
    int run = (tid == 0) ? 0 : part[tid - 1];
    for (int i = b; i < e; i++) {
        rowptr[i] = run;
        cursor[i] = run;
        run += cnt[i];
        cnt[i] = 0;                      // reset for next call
    }
    if (tid == 0) rowptr[n] = part[1023];
}

__global__ void scatter_kernel(const int* __restrict__ src, const int* __restrict__ dst,
                               const int* __restrict__ type, int E,
                               int* __restrict__ cursor, int2* __restrict__ cedge) {
    int i = blockIdx.x * blockDim.x + threadIdx.x;
    if (i < E) {
        int p = atomicAdd(&cursor[dst[i]], 1);
        cedge[p] = make_int2(src[i], type[i]);
    }
}

// relproj[layer][r][h]; grid = 2 blocks (one per layer)
__global__ void relproj_kernel(const float* __restrict__ rel_emb,
                               const float* __restrict__ line1,
                               const float* __restrict__ atte1,
                               const float* __restrict__ line2,
                               const float* __restrict__ atte2,
                               float* __restrict__ relproj) {
    const float* line = blockIdx.x ? line2 : line1;
    const float* atte = blockIdx.x ? atte2 : atte1;
    float* rp = relproj + blockIdx.x * 26 * HEADS;
    __shared__ float we[32 * HEADS];
    int tid = threadIdx.x;   // 128 threads
    {
        int k = tid >> 2, h = tid & 3;
        float s = 0.f;
        const float* lp = line + k * HD + h * DH;
        const float* ap = atte + h * DH;
        for (int d = 0; d < DH; d++) s += lp[d] * ap[d];
        we[k * HEADS + h] = s;
    }
    __syncthreads();
    if (tid < 26 * HEADS) {
        int r = tid >> 2, h = tid & 3;
        float s = 0.f;
        for (int k = 0; k < 32; k++) s += rel_emb[r * 32 + k] * we[k * HEADS + h];
        rp[tid] = s;
    }
}

// ---------------- tf32 tensor-core GEMM (cp.async, depth-2 lookahead) --------
// All inputs are pre-rounded to the tf32 grid, so fragments feed raw bits to
// the MMA (HW truncation is a no-op). No conversions in the hot loop.
__device__ __forceinline__ void mma_tf32(float c[4], const uint32_t a[4], const uint32_t b[2]) {
    asm volatile(
        "mma.sync.aligned.m16n8k8.row.col.f32.tf32.tf32.f32 "
        "{%0,%1,%2,%3}, {%4,%5,%6,%7}, {%8,%9}, {%0,%1,%2,%3};"
        : "+f"(c[0]), "+f"(c[1]), "+f"(c[2]), "+f"(c[3])
        : "r"(a[0]), "r"(a[1]), "r"(a[2]), "r"(a[3]), "r"(b[0]), "r"(b[1]));
}

__device__ __forceinline__ void cp4(uint32_t smem_u32, const float* gptr, bool pred) {
    int sz = pred ? 4 : 0;
    asm volatile("cp.async.ca.shared.global [%0], [%1], 4, %2;"
                 :: "r"(smem_u32), "l"(gptr), "r"(sz));
}
__device__ __forceinline__ void cp_commit() {
    asm volatile("cp.async.commit_group;");
}
template <int N>
__device__ __forceinline__ void cp_wait() {
    asm volatile("cp.async.wait_group %0;" :: "n"(N));
}

// C = act(A[M,K] @ B[K,N] + bias). BM=128 BN=128 BK=16, 8 warps (2m x 4n).
// !ATT epilogue stores tf32-rounded fp32 (outputs feed later GEMMs).
// ATT: BN==DH, blockIdx.x = head hh; stores fp16 hlinh + fused att dots.
template <bool RELU, bool HAS_BIAS, bool ATT>
__global__ __launch_bounds__(256, 2) void mma_gemm(
        int M, int N, int K,
        const float* __restrict__ A, const float* __restrict__ B,
        const float* __restrict__ bias, float* __restrict__ C,
        __half* __restrict__ Ch,
        const float* __restrict__ atts, const float* __restrict__ attd,
        float* __restrict__ as_, float* __restrict__ ad_) {
    constexpr int BM = 128, BN = 128, BK = 16;
    constexpr int AP = 20;    // A smem pitch: frag banks conflict-free
    constexpr int BP = 136;   // B smem pitch: frag banks conflict-free
    __shared__ float As[2][BM * AP];
    __shared__ float Bs[2][BK * BP];
    __shared__ float s_att[BM * 2];      // ATT reduction (1KB)

    const int tid  = threadIdx.x;
    const int lane = tid & 31;
    const int warp = tid >> 5;
    const int warpM = warp >> 2;
    const int warpN = warp & 3;
    const int bm = blockIdx.y * BM;
    const int bn = blockIdx.x * BN;
    const int mBase = warpM * 64;
    const int nBase = warpN * 32;
    const int qr = lane >> 2;
    const int qc = lane & 3;

    const uint32_t sA0 = (uint32_t)__cvta_generic_to_shared(&As[0][0]);
    const uint32_t sA1 = (uint32_t)__cvta_generic_to_shared(&As[1][0]);
    const uint32_t sB0 = (uint32_t)__cvta_generic_to_shared(&Bs[0][0]);
    const uint32_t sB1 = (uint32_t)__cvta_generic_to_shared(&Bs[1][0]);

    float acc[4][4][4] = {};

    auto issue = [&](int kt, int s) {
        const uint32_t aBase = s ? sA1 : sA0;
        const uint32_t bBase = s ? sB1 : sB0;
#pragma unroll
        for (int i = 0; i < 8; i++) {        // A: 128x16
            int idx = i * 256 + tid;
            int r = idx >> 4, c = idx & 15;
            int gr = bm + r, gc = kt + c;
            cp4(aBase + (uint32_t)(r * AP + c) * 4,
                A + (long)gr * K + gc, (gr < M) && (gc < K));
        }
#pragma unroll
        for (int i = 0; i < 8; i++) {        // B: 16x128
            int idx = i * 256 + tid;
            int r = idx >> 7, c = idx & 127;
            int gr = kt + r;
            cp4(bBase + (uint32_t)(r * BP + c) * 4,
                B + (long)gr * N + bn + c, gr < K);
        }
        cp_commit();
    };

    const int nkt = (K + BK - 1) / BK;
    issue(0, 0);
    if (nkt > 1) issue(BK, 1);

    int s = 0;
    for (int it = 0; it < nkt; it++, s ^= 1) {
        if (it + 1 < nkt) cp_wait<1>(); else cp_wait<0>();
        __syncthreads();

        const uint32_t* Acur = reinterpret_cast<const uint32_t*>(As[s]);
        const uint32_t* Bcur = reinterpret_cast<const uint32_t*>(Bs[s]);
#pragma unroll
        for (int ks = 0; ks < 2; ks++) {
            const int k0 = ks * 8 + qc;
            uint32_t af[4][4], bf[4][2];
#pragma unroll
            for (int am = 0; am < 4; am++) {
                int r0 = mBase + am * 16 + qr;
                af[am][0] = Acur[r0 * AP + k0];
                af[am][1] = Acur[(r0 + 8) * AP + k0];
                af[am][2] = Acur[r0 * AP + k0 + 4];
                af[am][3] = Acur[(r0 + 8) * AP + k0 + 4];
            }
#pragma unroll
            for (int bnn = 0; bnn < 4; bnn++) {
                int c0 = nBase + bnn * 8 + qr;
                bf[bnn][0] = Bcur[k0 * BP + c0];
                bf[bnn][1] = Bcur[(k0 + 4) * BP + c0];
            }
#pragma unroll
            for (int am = 0; am < 4; am++)
#pragma unroll
                for (int bnn = 0; bnn < 4; bnn++)
                    mma_tf32(acc[am][bnn], af[am], bf[bnn]);
        }
        __syncthreads();
        if (it + 2 < nkt) issue((it + 2) * BK, s);
    }

    // ---- epilogue ----
    if (!ATT) {
#pragma unroll
        for (int am = 0; am < 4; am++) {
            int r0 = bm + mBase + am * 16 + qr;
#pragma unroll
            for (int bnn = 0; bnn < 4; bnn++) {
                int c0 = bn + nBase + bnn * 8 + 2 * qc;
                float b0 = 0.f, b1 = 0.f;
                if (HAS_BIAS) { b0 = bias[c0]; b1 = bias[c0 + 1]; }
#pragma unroll
                for (int half = 0; half < 2; half++) {
                    int gr = r0 + half * 8;
                    if (gr >= M) continue;
                    float v0 = acc[am][bnn][half * 2 + 0] + b0;
                    float v1 = acc[am][bnn][half * 2 + 1] + b1;
                    if (RELU) { v0 = fmaxf(v0, 0.f); v1 = fmaxf(v1, 0.f); }
                    // outputs feed later GEMMs as A: keep them on the tf32 grid
                    v0 = rnd_tf32(v0); v1 = rnd_tf32(v1);
                    *reinterpret_cast<float2*>(&C[(long)gr * N + c0]) = make_float2(v0, v1);
                }
            }
        }
    } else {
        const int hh = blockIdx.x;                   // head (BN==DH==128)
        // fp16 store in agg layout: halves index = row*HD + L*16 + hh*4 + d
#pragma unroll
        for (int am = 0; am < 4; am++) {
            int r0 = bm + mBase + am * 16 + qr;
#pragma unroll
            for (int bnn = 0; bnn < 4; bnn++) {
                int cl = nBase + bnn * 8 + 2 * qc;   // head-local col (even)
                int L = cl >> 2, d = cl & 3;         // d in {0,2}
#pragma unroll
                for (int half = 0; half < 2; half++) {
                    int gr = r0 + half * 8;
                    if (gr >= M) continue;
                    float v0 = acc[am][bnn][half * 2 + 0];
                    float v1 = acc[am][bnn][half * 2 + 1];
                    __half2 hv = __floats2half2_rn(v0, v1);
                    *reinterpret_cast<__half2*>(
                        Ch + (long)gr * HD + L * 16 + hh * 4 + d) = hv;
                }
            }
        }
        // fused attention dots
        float w0s[4], w1s[4], w0d[4], w1d[4];
#pragma unroll
        for (int bnn = 0; bnn < 4; bnn++) {
            int cl = nBase + bnn * 8 + 2 * qc;
            w0s[bnn] = atts[hh * DH + cl];  w1s[bnn] = atts[hh * DH + cl + 1];
            w0d[bnn] = attd[hh * DH + cl];  w1d[bnn] = attd[hh * DH + cl + 1];
        }
        float ps[4][2], pd[4][2];
#pragma unroll
        for (int am = 0; am < 4; am++)
#pragma unroll
            for (int half = 0; half < 2; half++) {
                float s_ = 0.f, d_ = 0.f;
#pragma unroll
                for (int bnn = 0; bnn < 4; bnn++) {
                    float v0 = acc[am][bnn][half * 2 + 0];
                    float v1 = acc[am][bnn][half * 2 + 1];
                    s_ += v0 * w0s[bnn] + v1 * w1s[bnn];
                    d_ += v0 * w0d[bnn] + v1 * w1d[bnn];
                }
                ps[am][half] = s_; pd[am][half] = d_;
            }
#pragma unroll
        for (int off = 1; off <= 2; off <<= 1)
#pragma unroll
            for (int am = 0; am < 4; am++)
#pragma unroll
                for (int half = 0; half < 2; half++) {
                    ps[am][half] += __shfl_xor_sync(~0u, ps[am][half], off);
                    pd[am][half] += __shfl_xor_sync(~0u, pd[am][half], off);
                }
        s_att[tid] = 0.f;
        if (tid < BM * 2 - 256) s_att[256 + tid] = 0.f;
        __syncthreads();
        if (qc == 0) {
#pragma unroll
            for (int am = 0; am < 4; am++)
#pragma unroll
                for (int half = 0; half < 2; half++) {
                    int lr = mBase + am * 16 + qr + half * 8;   // 0..127
                    atomicAdd(&s_att[lr * 2 + 0], ps[am][half]);
                    atomicAdd(&s_att[lr * 2 + 1], pd[am][half]);
                }
        }
        __syncthreads();
        {
            int lr = tid >> 1, comp = tid & 1;
            int gr = bm + lr;
            if (gr < M) {
                float v = s_att[lr * 2 + comp];
                if (comp) ad_[gr * HEADS + hh] = v;
                else      as_[gr * HEADS + hh] = v;
            }
        }
    }
}

// ---------------- GAT aggregation: one WARP per destination node -------------
// hlinh layout: halves [n][L=0..31][head=0..3][d=0..3]; lane L reads its 32B
// (2 x LDG.128) per gathered node.
__device__ __forceinline__ float leaky02(float x) {
    return (x > 0.f) ? x : 0.2f * x;
}

__device__ __forceinline__ float4 unpack_head(uint32_t lo, uint32_t hi) {
    float2 a = __half22float2(*reinterpret_cast<const __half2*>(&lo));
    float2 b = __half22float2(*reinterpret_cast<const __half2*>(&hi));
    return make_float4(a.x, a.y, b.x, b.y);
}

__global__ __launch_bounds__(256) void gat_agg_kernel(
        const __half* __restrict__ hlinh,
        const float* __restrict__ a_s,
        const float* __restrict__ a_d,
        const int* __restrict__ rowptr,
        const int2* __restrict__ cedge,
        const float* __restrict__ relproj,
        const float* __restrict__ bias,
        float* __restrict__ out, int N, int round_out) {
    const int w    = threadIdx.x >> 5;     // warp in block (8)
    const int lane = threadIdx.x & 31;
    const int n    = blockIdx.x * 8 + w;

    __shared__ __align__(16) float s_rp[32 * HEADS];   // relproj table (26 used)
    __shared__ __align__(16) float s_l[8][CAP][HEADS]; // logits -> alphas (16KB)
    __shared__ int s_src[8][CAP];                      // cached src ids (4KB)

    if (threadIdx.x < 26 * HEADS) s_rp[threadIdx.x] = relproj[threadIdx.x];
    __syncthreads();
    if (n >= N) return;

    const int beg = rowptr[n], end = rowptr[n + 1];
    const int deg = end - beg;

    const float4 ad4 = *reinterpret_cast<const float4*>(a_d + n * HEADS);

    // ---- phase A: logits for all incoming edges (lanes parallel) ----
    float m0 = -1e30f, m1 = -1e30f, m2 = -1e30f, m3 = -1e30f;
    float s0 = 0.f, s1 = 0.f, s2 = 0.f, s3 = 0.f;
    float r0 = 0.f, r1 = 0.f, r2 = 0.f, r3 = 0.f;
    for (int j = lane; j < deg; j += 32) {
        const int2 st = cedge[beg + j];
        const int sp = st.x;
        const int tp = st.y;
        const float4 as4 = *reinterpret_cast<const float4*>(a_s + sp * HEADS);
        const float4 rp4 = *reinterpret_cast<const float4*>(s_rp + tp * HEADS);
        float l0 = leaky02(as4.x + ad4.x + rp4.x);
        float l1 = leaky02(as4.y + ad4.y + rp4.y);
        float l2 = leaky02(as4.z + ad4.z + rp4.z);
        float l3 = leaky02(as4.w + ad4.w + rp4.w);
        r0 += rp4.x; r1 += rp4.y; r2 += rp4.z; r3 += rp4.w;
        if (j < CAP) {
            s_src[w][j] = sp;
            *reinterpret_cast<float4*>(s_l[w][j]) = make_float4(l0, l1, l2, l3);
        }
        if (l0 > m0) { s0 = s0 * __expf(m0 - l0) + 1.f; m0 = l0; } else s0 += __expf(l0 - m0);
        if (l1 > m1) { s1 = s1 * __expf(m1 - l1) + 1.f; m1 = l1; } else s1 += __expf(l1 - m1);
        if (l2 > m2) { s2 = s2 * __expf(m2 - l2) + 1.f; m2 = l2; } else s2 += __expf(l2 - m2);
        if (l3 > m3) { s3 = s3 * __expf(m3 - l3) + 1.f; m3 = l3; } else s3 += __expf(l3 - m3);
    }
#pragma unroll
    for (int off = 16; off > 0; off >>= 1) {
        float mo, so;
        mo = __shfl_xor_sync(~0u, m0, off); so = __shfl_xor_sync(~0u, s0, off);
        if (mo > m0) { s0 = s0 * __expf(m0 - mo) + so; m0 = mo; } else s0 += so * __expf(mo - m0);
        mo = __shfl_xor_sync(~0u, m1, off); so = __shfl_xor_sync(~0u, s1, off);
        if (mo > m1) { s1 = s1 * __expf(m1 - mo) + so; m1 = mo; } else s1 += so * __expf(mo - m1);
        mo = __shfl_xor_sync(~0u, m2, off); so = __shfl_xor_sync(~0u, s2, off);
        if (mo > m2) { s2 = s2 * __expf(m2 - mo) + so; m2 = mo; } else s2 += so * __expf(mo - m2);
        mo = __shfl_xor_sync(~0u, m3, off); so = __shfl_xor_sync(~0u, s3, off);
        if (mo > m3) { s3 = s3 * __expf(m3 - mo) + so; m3 = mo; } else s3 += so * __expf(mo - m3);
        r0 += __shfl_xor_sync(~0u, r0, off);
        r1 += __shfl_xor_sync(~0u, r1, off);
        r2 += __shfl_xor_sync(~0u, r2, off);
        r3 += __shfl_xor_sync(~0u, r3, off);
    }

    // self loop: a_e = mean of relproj over incoming edges
    const float4 asn = *reinterpret_cast<const float4*>(a_s + n * HEADS);
    const float dinv = 1.f / (float)max(deg, 1);
    float ls0 = leaky02(asn.x + ad4.x + r0 * dinv);
    float ls1 = leaky02(asn.y + ad4.y + r1 * dinv);
    float ls2 = leaky02(asn.z + ad4.z + r2 * dinv);
    float ls3 = leaky02(asn.w + ad4.w + r3 * dinv);
    if (ls0 > m0) { s0 = s0 * __expf(m0 - ls0) + 1.f; m0 = ls0; } else s0 += __expf(ls0 - m0);
    if (ls1 > m1) { s1 = s1 * __expf(m1 - ls1) + 1.f; m1 = ls1; } else s1 += __expf(ls1 - m1);
    if (ls2 > m2) { s2 = s2 * __expf(m2 - ls2) + 1.f; m2 = ls2; } else s2 += __expf(ls2 - m2);
    if (ls3 > m3) { s3 = s3 * __expf(m3 - ls3) + 1.f; m3 = ls3; } else s3 += __expf(ls3 - m3);
    const float i0 = 1.f / (s0 + 1e-16f), i1 = 1.f / (s1 + 1e-16f);
    const float i2 = 1.f / (s2 + 1e-16f), i3 = 1.f / (s3 + 1e-16f);
    const float la0 = __expf(ls0 - m0) * i0, la1 = __expf(ls1 - m1) * i1;
    const float la2 = __expf(ls2 - m2) * i2, la3 = __expf(ls3 - m3) * i3;

    __syncwarp();
    const int ncached = min(deg, CAP);
    for (int j = lane; j < ncached; j += 32) {
        float4 l4 = *reinterpret_cast<float4*>(s_l[w][j]);
        l4.x = __expf(l4.x - m0) * i0;
        l4.y = __expf(l4.y - m1) * i1;
        l4.z = __expf(l4.z - m2) * i2;
        l4.w = __expf(l4.w - m3) * i3;
        *reinterpret_cast<float4*>(s_l[w][j]) = l4;
    }
    __syncwarp();

    // ---- phase B: lane L owns dims [4L,4L+4) per head; 2 x LDG.128 per edge.
    float4 a0, a1, a2, a3;
    {
        const uint4* hp = reinterpret_cast<const uint4*>(hlinh + (long)n * HD) + lane * 2;
        const uint4 p0 = hp[0], p1 = hp[1];
        float4 v0 = unpack_head(p0.x, p0.y);
        float4 v1 = unpack_head(p0.z, p0.w);
        float4 v2 = unpack_head(p1.x, p1.y);
        float4 v3 = unpack_head(p1.z, p1.w);
        a0 = make_float4(la0 * v0.x, la0 * v0.y, la0 * v0.z, la0 * v0.w);
        a1 = make_float4(la1 * v1.x, la1 * v1.y, la1 * v1.z, la1 * v1.w);
        a2 = make_float4(la2 * v2.x, la2 * v2.y, la2 * v2.z, la2 * v2.w);
        a3 = make_float4(la3 * v3.x, la3 * v3.y, la3 * v3.z, la3 * v3.w);
    }
#pragma unroll 4
    for (int j = 0; j < ncached; j++) {
        const int sp = s_src[w][j];
        const float4 al = *reinterpret_cast<const float4*>(s_l[w][j]);
        const uint4* hp = reinterpret_cast<const uint4*>(hlinh + (long)sp * HD) + lane * 2;
        const uint4 p0 = hp[0], p1 = hp[1];
        const float4 v0 = unpack_head(p0.x, p0.y);
        const float4 v1 = unpack_head(p0.z, p0.w);
        const float4 v2 = unpack_head(p1.x, p1.y);
        const float4 v3 = unpack_head(p1.z, p1.w);
        a0.x += al.x * v0.x; a0.y += al.x * v0.y; a0.z += al.x * v0.z; a0.w += al.x * v0.w;
        a1.x += al.y * v1.x; a1.y += al.y * v1.y; a1.z += al.y * v1.z; a1.w += al.y * v1.w;
        a2.x += al.z * v2.x; a2.y += al.z * v2.y; a2.z += al.z * v2.z; a2.w += al.z * v2.w;
        a3.x += al.w * v3.x; a3.y += al.w * v3.y; a3.z += al.w * v3.z; a3.w += al.w * v3.w;
    }
    // overflow tail (deg > CAP): recompute alphas
    for (int j = CAP; j < deg; j++) {
        const int2 st = cedge[beg + j];
        const int sp = st.x;
        const float4 as4 = *reinterpret_cast<const float4*>(a_s + sp * HEADS);
        const float4 rp4 = *reinterpret_cast<const float4*>(s_rp + st.y * HEADS);
        float4 al;
        al.x = __expf(leaky02(as4.x + ad4.x + rp4.x) - m0) * i0;
        al.y = __expf(leaky02(as4.y + ad4.y + rp4.y) - m1) * i1;
        al.z = __expf(leaky02(as4.z + ad4.z + rp4.z) - m2) * i2;
        al.w = __expf(leaky02(as4.w + ad4.w + rp4.w) - m3) * i3;
        const uint4* hp = reinterpret_cast<const uint4*>(hlinh + (long)sp * HD) + lane * 2;
        const uint4 p0 = hp[0], p1 = hp[1];
        const float4 v0 = unpack_head(p0.x, p0.y);
        const float4 v1 = unpack_head(p0.z, p0.w);
        const float4 v2 = unpack_head(p1.x, p1.y);
        const float4 v3 = unpack_head(p1.z, p1.w);
        a0.x += al.x * v0.x; a0.y += al.x * v0.y; a0.z += al.x * v0.z; a0.w += al.x * v0.w;
        a1.x += al.y * v1.x; a1.y += al.y * v1.y; a1.z += al.y * v1.z; a1.w += al.y * v1.w;
        a2.x += al.z * v2.x; a2.y += al.z * v2.y; a2.z += al.z * v2.z; a2.w += al.z * v2.w;
        a3.x += al.w * v3.x; a3.y += al.w * v3.y; a3.z += al.w * v3.z; a3.w += al.w * v3.w;
    }

    const float4 b4 = *reinterpret_cast<const float4*>(bias + 4 * lane);
    float4 o;
    o.x = fmaxf(0.25f * (a0.x + a1.x + a2.x + a3.x) + b4.x, 0.f);
    o.y = fmaxf(0.25f * (a0.y + a1.y + a2.y + a3.y) + b4.y, 0.f);
    o.z = fmaxf(0.25f * (a0.z + a1.z + a2.z + a3.z) + b4.z, 0.f);
    o.w = fmaxf(0.25f * (a0.w + a1.w + a2.w + a3.w) + b4.w, 0.f);
    if (round_out) {   // h1 feeds GEMM-L2 as A: keep on tf32 grid
        o.x = rnd_tf32(o.x); o.y = rnd_tf32(o.y);
        o.z = rnd_tf32(o.z); o.w = rnd_tf32(o.w);
    }
    *reinterpret_cast<float4*>(out + (long)n * DH + 4 * lane) = o;
}

// ---------------- launch ------------------------------------------------------
extern "C" void kernel_launch(void* const* d_in, const int* in_sizes, int n_in,
                              void* d_out, int out_size) {
    const float* x     = (const float*)d_in[0];
    const int*   eidx  = (const int*)d_in[1];
    const int*   etype = (const int*)d_in[2];
    const float* w1    = (const float*)d_in[3];
    const float* b1    = (const float*)d_in[4];
    const float* w2    = (const float*)d_in[5];
    const float* b2    = (const float*)d_in[6];
    const float* rel   = (const float*)d_in[7];
    const float* lin1  = (const float*)d_in[8];
    const float* line1 = (const float*)d_in[9];
    const float* atts1 = (const float*)d_in[10];
    const float* attd1 = (const float*)d_in[11];
    const float* atte1 = (const float*)d_in[12];
    const float* bias1 = (const float*)d_in[13];
    const float* lin2  = (const float*)d_in[14];
    const float* line2 = (const float*)d_in[15];
    const float* atts2 = (const float*)d_in[16];
    const float* attd2 = (const float*)d_in[17];
    const float* atte2 = (const float*)d_in[18];
    const float* bias2 = (const float*)d_in[19];

    const int N = out_size / DH;          // 20000
    const int E = in_sizes[1] / 2;        // 320000
    const int F = in_sizes[3] / 256;      // 518
    const int* src = eidx;
    const int* dst = eidx + E;

    float *xr, *wr, *hidden, *h0, *h1, *as_, *ad_, *relproj;
    __half* hlinh;
    int *cnt, *cursor, *rowptr;
    int2* cedge;
    cudaGetSymbolAddress((void**)&xr, g_xr);
    cudaGetSymbolAddress((void**)&wr, g_wr);
    cudaGetSymbolAddress((void**)&hidden, g_hidden);
    cudaGetSymbolAddress((void**)&h0, g_h0);
    cudaGetSymbolAddress((void**)&h1, g_h1);
    cudaGetSymbolAddress((void**)&hlinh, g_hlinh);
    cudaGetSymbolAddress((void**)&as_, g_as);
    cudaGetSymbolAddress((void**)&ad_, g_ad);
    cudaGetSymbolAddress((void**)&cnt, g_cnt);
    cudaGetSymbolAddress((void**)&cursor, g_cursor);
    cudaGetSymbolAddress((void**)&rowptr, g_rowptr);
    cudaGetSymbolAddress((void**)&cedge, g_cedge);
    cudaGetSymbolAddress((void**)&relproj, g_relproj);

    const long nx  = (long)N * F;
    const long nw1 = (long)F * 256;
    const long nw2 = 256 * DH;
    const long nl  = DH * HD;
    float* w1r = wr;
    float* w2r = wr + nw1;
    float* l1r = wr + nw1 + nw2;
    float* l2r = wr + nw1 + nw2 + nl;

    const int MB = (N + 127) / 128;
    const int AGG_B = (N + 7) / 8;

    // 1: hist + tf32 pre-rounding of x and all GEMM B matrices
    hist_round_kernel<<<(E + 255) / 256, 256>>>(dst, E, cnt,
                                                x, xr, nx, w1, nw1, w2, nw2,
                                                lin1, nl, lin2, wr);
    // 2-3: CSR build
    scan_kernel<<<1, 1024>>>(cnt, rowptr, cursor, N);
    scatter_kernel<<<(E + 255) / 256, 256>>>(src, dst, etype, E, cursor, cedge);

    // 4: encoder GEMM 1 (captured by ncu slot)
    {
        dim3 g(256 / 128, MB);
        mma_gemm<true, true, false><<<g, 256>>>(N, 256, F, xr, w1r, b1, hidden,
                                                nullptr, nullptr, nullptr, nullptr, nullptr);
    }
    // 5: encoder GEMM 2
    {
        dim3 g(1, MB);
        mma_gemm<false, true, false><<<g, 256>>>(N, DH, 256, hidden, w2r, b2, h0,
                                                 nullptr, nullptr, nullptr, nullptr, nullptr);
    }

    // 6: collapsed edge-attention tables (both layers, one launch)
    relproj_kernel<<<2, 128>>>(rel, line1, atte1, line2, atte2, relproj);

    // 7-8: GAT layer 1
    {
        dim3 g(HD / 128, MB);
        mma_gemm<false, false, true><<<g, 256>>>(N, HD, DH, h0, l1r, nullptr, nullptr,
                                                 hlinh, atts1, attd1, as_, ad_);
    }
    gat_agg_kernel<<<AGG_B, 256>>>(hlinh, as_, ad_, rowptr, cedge,
                                   relproj, bias1, h1, N, 1);

    // 9-10: GAT layer 2
    {
        dim3 g(HD / 128, MB);
        mma_gemm<false, false, true><<<g, 256>>>(N, HD, DH, h1, l2r, nullptr, nullptr,
                                                 hlinh, atts2, attd2, as_, ad_);
    }
    gat_agg_kernel<<<AGG_B, 256>>>(hlinh, as_, ad_, rowptr, cedge,
                                   relproj + 26 * HEADS, bias2, (float*)d_out, N, 0);
}

// round 10
// speedup vs baseline: 1.0866x; 1.0866x over previous
#include <cuda_runtime.h>
#include <cuda_fp16.h>
#include <cstdint>

// ---------------- problem-size bounds (fixed by the dataset) ----------------
#define NMAX 20000
#define EMAX 320000
#define FIN  518
#define DH   128     // node embedding dim
#define HEADS 4
#define HD   512     // HEADS * DH
#define CAP  128     // cached edges per node (overflow recomputed)

// ---------------- device scratch (no allocations allowed) -------------------
__device__ float  g_wr[FIN * 256 + 256 * DH + 2 * DH * HD];  // RNA-rounded weights
__device__ float  g_hidden[NMAX * 256];   // encoder hidden (tf32 grid)
__device__ float  g_h0[NMAX * DH];        // encoder out (tf32 grid)
__device__ float  g_h1[NMAX * DH];        // layer1 out (tf32 grid)
__device__ __half g_hlinh[NMAX * HD];     // h @ lin in fp16, layout [n][L][head][4]
__device__ float  g_as[NMAX * HEADS];
__device__ float  g_ad[NMAX * HEADS];
__device__ int    g_cnt[NMAX];            // zero at load; re-zeroed by scan each call
__device__ int    g_cursor[NMAX];         // scatter cursors (scan initializes)
__device__ int    g_rowptr[NMAX + 1];
__device__ int2   g_cedge[EMAX];               // packed {src, type} per CSR slot
__device__ float  g_relproj[2 * 26 * HEADS];   // [layer][26][4]

__device__ __forceinline__ uint32_t f2tf32(float f) {
    uint32_t u;
    asm("cvt.rna.tf32.f32 %0, %1;" : "=r"(u) : "f"(f));
    return u;
}
__device__ __forceinline__ float rnd_tf32(float f) {
    return __uint_as_float(f2tf32(f));
}

// ---------------- hist + weight tf32 rounding (fused; weights are tiny) ------
__global__ void hist_round_kernel(const int* __restrict__ dst, int E,
                                  int* __restrict__ cnt,
                                  const float* __restrict__ w1, long nw1,
                                  const float* __restrict__ w2, long nw2,
                                  const float* __restrict__ l1, long nl,
                                  const float* __restrict__ l2,
                                  float* __restrict__ wr) {
    long gid = blockIdx.x * (long)blockDim.x + threadIdx.x;
    if (gid < E) atomicAdd(&cnt[dst[gid]], 1);
    const long stride = (long)gridDim.x * blockDim.x;
    const long total = nw1 + nw2 + 2 * nl;
    for (long j = gid; j < total; j += stride) {
        long i = j;
        if (i < nw1)      { wr[i] = rnd_tf32(w1[i]); continue; }
        i -= nw1;
        if (i < nw2)      { wr[nw1 + i] = rnd_tf32(w2[i]); continue; }
        i -= nw2;
        if (i < nl)       { wr[nw1 + nw2 + i] = rnd_tf32(l1[i]); continue; }
        i -= nl;
        wr[nw1 + nw2 + nl + i] = rnd_tf32(l2[i]);
    }
}

// single-block exclusive scan of cnt[0..n) -> rowptr[0..n] and cursor[0..n).
// Also zeroes cnt (so the next invocation's hist starts from zero).
__global__ void scan_kernel(int* __restrict__ cnt, int* __restrict__ rowptr,
                            int* __restrict__ cursor, int n) {
    __shared__ int part[1024];
    int tid = threadIdx.x;
    int chunk = (n + 1023) / 1024;
    int b = tid * chunk;
    int e = min(b + chunk, n);
    int s = 0;
    for (int i = b; i < e; i++) { s += cnt[i]; }
    part[tid] = s;
    __syncthreads();
    for (int off = 1; off < 1024; off <<= 1) {
        int v = (tid >= off) ? part[tid - off] : 0;
        __syncthreads();
        part[tid] += v;
        __syncthreads();
    }
    int run = (tid == 0) ? 0 : part[tid - 1];
    for (int i = b; i < e; i++) {
        rowptr[i] = run;
        cursor[i] = run;
        run += cnt[i];
        cnt[i] = 0;                      // reset for next call
    }
    if (tid == 0) rowptr[n] = part[1023];
}

__global__ void scatter_kernel(const int* __restrict__ src, const int* __restrict__ dst,
                               const int* __restrict__ type, int E,
                               int* __restrict__ cursor, int2* __restrict__ cedge) {
    int i = blockIdx.x * blockDim.x + threadIdx.x;
    if (i < E) {
        int p = atomicAdd(&cursor[dst[i]], 1);
        cedge[p] = make_int2(src[i], type[i]);
    }
}

// relproj[layer][r][h]; grid = 2 blocks (one per layer)
__global__ void relproj_kernel(const float* __restrict__ rel_emb,
                               const float* __restrict__ line1,
                               const float* __restrict__ atte1,
                               const float* __restrict__ line2,
                               const float* __restrict__ atte2,
                               float* __restrict__ relproj) {
    const float* line = blockIdx.x ? line2 : line1;
    const float* atte = blockIdx.x ? atte2 : atte1;
    float* rp = relproj + blockIdx.x * 26 * HEADS;
    __shared__ float we[32 * HEADS];
    int tid = threadIdx.x;   // 128 threads
    {
        int k = tid >> 2, h = tid & 3;
        float s = 0.f;
        const float* lp = line + k * HD + h * DH;
        const float* ap = atte + h * DH;
        for (int d = 0; d < DH; d++) s += lp[d] * ap[d];
        we[k * HEADS + h] = s;
    }
    __syncthreads();
    if (tid < 26 * HEADS) {
        int r = tid >> 2, h = tid & 3;
        float s = 0.f;
        for (int k = 0; k < 32; k++) s += rel_emb[r * 32 + k] * we[k * HEADS + h];
        rp[tid] = s;
    }
}

// ---------------- tf32 tensor-core GEMM (cp.async + vector fragments) --------
__device__ __forceinline__ void mma_tf32s(float c[4],
        uint32_t a0, uint32_t a1, uint32_t a2, uint32_t a3,
        uint32_t b0, uint32_t b1) {
    asm volatile(
        "mma.sync.aligned.m16n8k8.row.col.f32.tf32.tf32.f32 "
        "{%0,%1,%2,%3}, {%4,%5,%6,%7}, {%8,%9}, {%0,%1,%2,%3};"
        : "+f"(c[0]), "+f"(c[1]), "+f"(c[2]), "+f"(c[3])
        : "r"(a0), "r"(a1), "r"(a2), "r"(a3), "r"(b0), "r"(b1));
}

__device__ __forceinline__ void cp4(uint32_t smem_u32, const float* gptr, bool pred) {
    int sz = pred ? 4 : 0;
    asm volatile("cp.async.ca.shared.global [%0], [%1], 4, %2;"
                 :: "r"(smem_u32), "l"(gptr), "r"(sz));
}
__device__ __forceinline__ void cp_commit() {
    asm volatile("cp.async.commit_group;");
}
template <int N>
__device__ __forceinline__ void cp_wait() {
    asm volatile("cp.async.wait_group %0;" :: "n"(N));
}

// C = act(A[M,K] @ B[K,N] + bias). BM=128 BN=128 BK=16, 8 warps (2m x 4n).
// Fragment-friendly smem layouts (k-permuted) so the inner loop is
// 12 x LDS.128 + 32 x MMA with zero conversions:
//   A: As[r*16 + permA(c)], permA(c) = ((c&3)<<2)|((c>>2)&1)|(((c>>3)&1)<<1)
//   B: Bs[(k&3)*520 + c*4 + (k>>2)]
// !ATT epilogue stores tf32-RNA-rounded fp32 (outputs feed later GEMMs as A).
// ATT: BN==DH, blockIdx.x = head hh; stores fp16 hlinh + fused att dots.
template <bool RELU, bool HAS_BIAS, bool ATT>
__global__ __launch_bounds__(256, 2) void mma_gemm(
        int M, int N, int K,
        const float* __restrict__ A, const float* __restrict__ B,
        const float* __restrict__ bias, float* __restrict__ C,
        __half* __restrict__ Ch,
        const float* __restrict__ atts, const float* __restrict__ attd,
        float* __restrict__ as_, float* __restrict__ ad_) {
    constexpr int BM = 128, BN = 128, BK = 16;
    constexpr int APW = 16;     // A words per row (permuted k)
    constexpr int BPW = 520;    // B words per (k&3) group (pitch 520 = 8 mod 32)
    __shared__ uint32_t As[2][BM * APW];
    __shared__ uint32_t Bs[2][4 * BPW];
    __shared__ float s_att[BM * 2];      // ATT reduction (1KB)

    const int tid  = threadIdx.x;
    const int lane = tid & 31;
    const int warp = tid >> 5;
    const int warpM = warp >> 2;
    const int warpN = warp & 3;
    const int bm = blockIdx.y * BM;
    const int bn = blockIdx.x * BN;
    const int mBase = warpM * 64;
    const int nBase = warpN * 32;
    const int qr = lane >> 2;
    const int qc = lane & 3;

    const uint32_t sA0 = (uint32_t)__cvta_generic_to_shared(&As[0][0]);
    const uint32_t sA1 = (uint32_t)__cvta_generic_to_shared(&As[1][0]);
    const uint32_t sB0 = (uint32_t)__cvta_generic_to_shared(&Bs[0][0]);
    const uint32_t sB1 = (uint32_t)__cvta_generic_to_shared(&Bs[1][0]);

    float acc[4][4][4] = {};

    auto issue = [&](int kt, int s) {
        const uint32_t aBase = s ? sA1 : sA0;
        const uint32_t bBase = s ? sB1 : sB0;
#pragma unroll
        for (int i = 0; i < 8; i++) {        // A: 128x16
            int idx = i * 256 + tid;
            int r = idx >> 4, c = idx & 15;
            int gr = bm + r, gc = kt + c;
            int perm = ((c & 3) << 2) | ((c >> 2) & 1) | (((c >> 3) & 1) << 1);
            cp4(aBase + (uint32_t)(r * APW + perm) * 4,
                A + (long)gr * K + gc, (gr < M) && (gc < K));
        }
#pragma unroll
        for (int i = 0; i < 8; i++) {        // B: 16x128
            int idx = i * 256 + tid;
            int r = idx >> 7, c = idx & 127;
            int gr = kt + r;
            cp4(bBase + (uint32_t)((r & 3) * BPW + c * 4 + (r >> 2)) * 4,
                B + (long)gr * N + bn + c, gr < K);
        }
        cp_commit();
    };

    const int nkt = (K + BK - 1) / BK;
    issue(0, 0);
    if (nkt > 1) issue(BK, 1);

    int s = 0;
    for (int it = 0; it < nkt; it++, s ^= 1) {
        if (it + 1 < nkt) cp_wait<1>(); else cp_wait<0>();
        __syncthreads();

        const uint32_t* Acur = As[s];
        const uint32_t* Bcur = Bs[s];
        uint4 aLo[4], aHi[4], bF[4];
#pragma unroll
        for (int am = 0; am < 4; am++) {
            int r0 = mBase + am * 16 + qr;
            aLo[am] = *reinterpret_cast<const uint4*>(Acur + r0 * APW + qc * 4);
            aHi[am] = *reinterpret_cast<const uint4*>(Acur + (r0 + 8) * APW + qc * 4);
        }
#pragma unroll
        for (int bnn = 0; bnn < 4; bnn++) {
            int c0 = nBase + bnn * 8 + qr;
            bF[bnn] = *reinterpret_cast<const uint4*>(Bcur + qc * BPW + c0 * 4);
        }
#pragma unroll
        for (int am = 0; am < 4; am++)
#pragma unroll
            for (int bnn = 0; bnn < 4; bnn++)
                mma_tf32s(acc[am][bnn], aLo[am].x, aHi[am].x, aLo[am].y, aHi[am].y,
                          bF[bnn].x, bF[bnn].y);
#pragma unroll
        for (int am = 0; am < 4; am++)
#pragma unroll
            for (int bnn = 0; bnn < 4; bnn++)
                mma_tf32s(acc[am][bnn], aLo[am].z, aHi[am].z, aLo[am].w, aHi[am].w,
                          bF[bnn].z, bF[bnn].w);
        __syncthreads();
        if (it + 2 < nkt) issue((it + 2) * BK, s);
    }

    // ---- epilogue ----
    if (!ATT) {
#pragma unroll
        for (int am = 0; am < 4; am++) {
            int r0 = bm + mBase + am * 16 + qr;
#pragma unroll
            for (int bnn = 0; bnn < 4; bnn++) {
                int c0 = bn + nBase + bnn * 8 + 2 * qc;
                float b0 = 0.f, b1 = 0.f;
                if (HAS_BIAS) { b0 = bias[c0]; b1 = bias[c0 + 1]; }
#pragma unroll
                for (int half = 0; half < 2; half++) {
                    int gr = r0 + half * 8;
                    if (gr >= M) continue;
                    float v0 = acc[am][bnn][half * 2 + 0] + b0;
                    float v1 = acc[am][bnn][half * 2 + 1] + b1;
                    if (RELU) { v0 = fmaxf(v0, 0.f); v1 = fmaxf(v1, 0.f); }
                    // outputs feed later GEMMs as A: keep them on the tf32 grid
                    v0 = rnd_tf32(v0); v1 = rnd_tf32(v1);
                    *reinterpret_cast<float2*>(&C[(long)gr * N + c0]) = make_float2(v0, v1);
                }
            }
        }
    } else {
        const int hh = blockIdx.x;                   // head (BN==DH==128)
        // fp16 store in agg layout: halves index = row*HD + L*16 + hh*4 + d
#pragma unroll
        for (int am = 0; am < 4; am++) {
            int r0 = bm + mBase + am * 16 + qr;
#pragma unroll
            for (int bnn = 0; bnn < 4; bnn++) {
                int cl = nBase + bnn * 8 + 2 * qc;   // head-local col (even)
                int L = cl >> 2, d = cl & 3;         // d in {0,2}
#pragma unroll
                for (int half = 0; half < 2; half++) {
                    int gr = r0 + half * 8;
                    if (gr >= M) continue;
                    float v0 = acc[am][bnn][half * 2 + 0];
                    float v1 = acc[am][bnn][half * 2 + 1];
                    __half2 hv = __floats2half2_rn(v0, v1);
                    *reinterpret_cast<__half2*>(
                        Ch + (long)gr * HD + L * 16 + hh * 4 + d) = hv;
                }
            }
        }
        // fused attention dots
        float w0s[4], w1s[4], w0d[4], w1d[4];
#pragma unroll
        for (int bnn = 0; bnn < 4; bnn++) {
            int cl = nBase + bnn * 8 + 2 * qc;
            w0s[bnn] = atts[hh * DH + cl];  w1s[bnn] = atts[hh * DH + cl + 1];
            w0d[bnn] = attd[hh * DH + cl];  w1d[bnn] = attd[hh * DH + cl + 1];
        }
        float ps[4][2], pd[4][2];
#pragma unroll
        for (int am = 0; am < 4; am++)
#pragma unroll
            for (int half = 0; half < 2; half++) {
                float s_ = 0.f, d_ = 0.f;
#pragma unroll
                for (int bnn = 0; bnn < 4; bnn++) {
                    float v0 = acc[am][bnn][half * 2 + 0];
                    float v1 = acc[am][bnn][half * 2 + 1];
                    s_ += v0 * w0s[bnn] + v1 * w1s[bnn];
                    d_ += v0 * w0d[bnn] + v1 * w1d[bnn];
                }
                ps[am][half] = s_; pd[am][half] = d_;
            }
#pragma unroll
        for (int off = 1; off <= 2; off <<= 1)
#pragma unroll
            for (int am = 0; am < 4; am++)
#pragma unroll
                for (int half = 0; half < 2; half++) {
                    ps[am][half] += __shfl_xor_sync(~0u, ps[am][half], off);
                    pd[am][half] += __shfl_xor_sync(~0u, pd[am][half], off);
                }
        s_att[tid] = 0.f;
        if (tid < BM * 2 - 256) s_att[256 + tid] = 0.f;
        __syncthreads();
        if (qc == 0) {
#pragma unroll
            for (int am = 0; am < 4; am++)
#pragma unroll
                for (int half = 0; half < 2; half++) {
                    int lr = mBase + am * 16 + qr + half * 8;   // 0..127
                    atomicAdd(&s_att[lr * 2 + 0], ps[am][half]);
                    atomicAdd(&s_att[lr * 2 + 1], pd[am][half]);
                }
        }
        __syncthreads();
        {
            int lr = tid >> 1, comp = tid & 1;
            int gr = bm + lr;
            if (gr < M) {
                float v = s_att[lr * 2 + comp];
                if (comp) ad_[gr * HEADS + hh] = v;
                else      as_[gr * HEADS + hh] = v;
            }
        }
    }
}

// ---------------- GAT aggregation: one WARP per destination node -------------
__device__ __forceinline__ float leaky02(float x) {
    return (x > 0.f) ? x : 0.2f * x;
}

__device__ __forceinline__ float4 unpack_head(uint32_t lo, uint32_t hi) {
    float2 a = __half22float2(*reinterpret_cast<const __half2*>(&lo));
    float2 b = __half22float2(*reinterpret_cast<const __half2*>(&hi));
    return make_float4(a.x, a.y, b.x, b.y);
}

__global__ __launch_bounds__(256) void gat_agg_kernel(
        const __half* __restrict__ hlinh,
        const float* __restrict__ a_s,
        const float* __restrict__ a_d,
        const int* __restrict__ rowptr,
        const int2* __restrict__ cedge,
        const float* __restrict__ relproj,
        const float* __restrict__ bias,
        float* __restrict__ out, int N, int round_out) {
    const int w    = threadIdx.x >> 5;     // warp in block (8)
    const int lane = threadIdx.x & 31;
    const int n    = blockIdx.x * 8 + w;

    __shared__ __align__(16) float s_rp[32 * HEADS];   // relproj table (26 used)
    __shared__ __align__(16) float s_l[8][CAP][HEADS]; // logits -> alphas (16KB)
    __shared__ int s_src[8][CAP];                      // cached src ids (4KB)

    if (threadIdx.x < 26 * HEADS) s_rp[threadIdx.x] = relproj[threadIdx.x];
    __syncthreads();
    if (n >= N) return;

    const int beg = rowptr[n], end = rowptr[n + 1];
    const int deg = end - beg;

    const float4 ad4 = *reinterpret_cast<const float4*>(a_d + n * HEADS);

    // ---- phase A: logits for all incoming edges (lanes parallel) ----
    float m0 = -1e30f, m1 = -1e30f, m2 = -1e30f, m3 = -1e30f;
    float s0 = 0.f, s1 = 0.f, s2 = 0.f, s3 = 0.f;
    float r0 = 0.f, r1 = 0.f, r2 = 0.f, r3 = 0.f;
    for (int j = lane; j < deg; j += 32) {
        const int2 st = cedge[beg + j];
        const int sp = st.x;
        const int tp = st.y;
        const float4 as4 = *reinterpret_cast<const float4*>(a_s + sp * HEADS);
        const float4 rp4 = *reinterpret_cast<const float4*>(s_rp + tp * HEADS);
        float l0 = leaky02(as4.x + ad4.x + rp4.x);
        float l1 = leaky02(as4.y + ad4.y + rp4.y);
        float l2 = leaky02(as4.z + ad4.z + rp4.z);
        float l3 = leaky02(as4.w + ad4.w + rp4.w);
        r0 += rp4.x; r1 += rp4.y; r2 += rp4.z; r3 += rp4.w;
        if (j < CAP) {
            s_src[w][j] = sp;
            *reinterpret_cast<float4*>(s_l[w][j]) = make_float4(l0, l1, l2, l3);
        }
        if (l0 > m0) { s0 = s0 * __expf(m0 - l0) + 1.f; m0 = l0; } else s0 += __expf(l0 - m0);
        if (l1 > m1) { s1 = s1 * __expf(m1 - l1) + 1.f; m1 = l1; } else s1 += __expf(l1 - m1);
        if (l2 > m2) { s2 = s2 * __expf(m2 - l2) + 1.f; m2 = l2; } else s2 += __expf(l2 - m2);
        if (l3 > m3) { s3 = s3 * __expf(m3 - l3) + 1.f; m3 = l3; } else s3 += __expf(l3 - m3);
    }
#pragma unroll
    for (int off = 16; off > 0; off >>= 1) {
        float mo, so;
        mo = __shfl_xor_sync(~0u, m0, off); so = __shfl_xor_sync(~0u, s0, off);
        if (mo > m0) { s0 = s0 * __expf(m0 - mo) + so; m0 = mo; } else s0 += so * __expf(mo - m0);
        mo = __shfl_xor_sync(~0u, m1, off); so = __shfl_xor_sync(~0u, s1, off);
        if (mo > m1) { s1 = s1 * __expf(m1 - mo) + so; m1 = mo; } else s1 += so * __expf(mo - m1);
        mo = __shfl_xor_sync(~0u, m2, off); so = __shfl_xor_sync(~0u, s2, off);
        if (mo > m2) { s2 = s2 * __expf(m2 - mo) + so; m2 = mo; } else s2 += so * __expf(mo - m2);
        mo = __shfl_xor_sync(~0u, m3, off); so = __shfl_xor_sync(~0u, s3, off);
        if (mo > m3) { s3 = s3 * __expf(m3 - mo) + so; m3 = mo; } else s3 += so * __expf(mo - m3);
        r0 += __shfl_xor_sync(~0u, r0, off);
        r1 += __shfl_xor_sync(~0u, r1, off);
        r2 += __shfl_xor_sync(~0u, r2, off);
        r3 += __shfl_xor_sync(~0u, r3, off);
    }

    // self loop: a_e = mean of relproj over incoming edges
    const float4 asn = *reinterpret_cast<const float4*>(a_s + n * HEADS);
    const float dinv = 1.f / (float)max(deg, 1);
    float ls0 = leaky02(asn.x + ad4.x + r0 * dinv);
    float ls1 = leaky02(asn.y + ad4.y + r1 * dinv);
    float ls2 = leaky02(asn.z + ad4.z + r2 * dinv);
    float ls3 = leaky02(asn.w + ad4.w + r3 * dinv);
    if (ls0 > m0) { s0 = s0 * __expf(m0 - ls0) + 1.f; m0 = ls0; } else s0 += __expf(ls0 - m0);
    if (ls1 > m1) { s1 = s1 * __expf(m1 - ls1) + 1.f; m1 = ls1; } else s1 += __expf(ls1 - m1);
    if (ls2 > m2) { s2 = s2 * __expf(m2 - ls2) + 1.f; m2 = ls2; } else s2 += __expf(ls2 - m2);
    if (ls3 > m3) { s3 = s3 * __expf(m3 - ls3) + 1.f; m3 = ls3; } else s3 += __expf(ls3 - m3);
    const float i0 = 1.f / (s0 + 1e-16f), i1 = 1.f / (s1 + 1e-16f);
    const float i2 = 1.f / (s2 + 1e-16f), i3 = 1.f / (s3 + 1e-16f);
    const float la0 = __expf(ls0 - m0) * i0, la1 = __expf(ls1 - m1) * i1;
    const float la2 = __expf(ls2 - m2) * i2, la3 = __expf(ls3 - m3) * i3;

    __syncwarp();
    const int ncached = min(deg, CAP);
    for (int j = lane; j < ncached; j += 32) {
        float4 l4 = *reinterpret_cast<float4*>(s_l[w][j]);
        l4.x = __expf(l4.x - m0) * i0;
        l4.y = __expf(l4.y - m1) * i1;
        l4.z = __expf(l4.z - m2) * i2;
        l4.w = __expf(l4.w - m3) * i3;
        *reinterpret_cast<float4*>(s_l[w][j]) = l4;
    }
    __syncwarp();

    // ---- phase B: lane L owns dims [4L,4L+4) per head; 2 x LDG.128 per edge.
    float4 a0, a1, a2, a3;
    {
        const uint4* hp = reinterpret_cast<const uint4*>(hlinh + (long)n * HD) + lane * 2;
        const uint4 p0 = hp[0], p1 = hp[1];
        float4 v0 = unpack_head(p0.x, p0.y);
        float4 v1 = unpack_head(p0.z, p0.w);
        float4 v2 = unpack_head(p1.x, p1.y);
        float4 v3 = unpack_head(p1.z, p1.w);
        a0 = make_float4(la0 * v0.x, la0 * v0.y, la0 * v0.z, la0 * v0.w);
        a1 = make_float4(la1 * v1.x, la1 * v1.y, la1 * v1.z, la1 * v1.w);
        a2 = make_float4(la2 * v2.x, la2 * v2.y, la2 * v2.z, la2 * v2.w);
        a3 = make_float4(la3 * v3.x, la3 * v3.y, la3 * v3.z, la3 * v3.w);
    }
#pragma unroll 4
    for (int j = 0; j < ncached; j++) {
        const int sp = s_src[w][j];
        const float4 al = *reinterpret_cast<const float4*>(s_l[w][j]);
        const uint4* hp = reinterpret_cast<const uint4*>(hlinh + (long)sp * HD) + lane * 2;
        const uint4 p0 = hp[0], p1 = hp[1];
        const float4 v0 = unpack_head(p0.x, p0.y);
        const float4 v1 = unpack_head(p0.z, p0.w);
        const float4 v2 = unpack_head(p1.x, p1.y);
        const float4 v3 = unpack_head(p1.z, p1.w);
        a0.x += al.x * v0.x; a0.y += al.x * v0.y; a0.z += al.x * v0.z; a0.w += al.x * v0.w;
        a1.x += al.y * v1.x; a1.y += al.y * v1.y; a1.z += al.y * v1.z; a1.w += al.y * v1.w;
        a2.x += al.z * v2.x; a2.y += al.z * v2.y; a2.z += al.z * v2.z; a2.w += al.z * v2.w;
        a3.x += al.w * v3.x; a3.y += al.w * v3.y; a3.z += al.w * v3.z; a3.w += al.w * v3.w;
    }
    // overflow tail (deg > CAP): recompute alphas
    for (int j = CAP; j < deg; j++) {
        const int2 st = cedge[beg + j];
        const int sp = st.x;
        const float4 as4 = *reinterpret_cast<const float4*>(a_s + sp * HEADS);
        const float4 rp4 = *reinterpret_cast<const float4*>(s_rp + st.y * HEADS);
        float4 al;
        al.x = __expf(leaky02(as4.x + ad4.x + rp4.x) - m0) * i0;
        al.y = __expf(leaky02(as4.y + ad4.y + rp4.y) - m1) * i1;
        al.z = __expf(leaky02(as4.z + ad4.z + rp4.z) - m2) * i2;
        al.w = __expf(leaky02(as4.w + ad4.w + rp4.w) - m3) * i3;
        const uint4* hp = reinterpret_cast<const uint4*>(hlinh + (long)sp * HD) + lane * 2;
        const uint4 p0 = hp[0], p1 = hp[1];
        const float4 v0 = unpack_head(p0.x, p0.y);
        const float4 v1 = unpack_head(p0.z, p0.w);
        const float4 v2 = unpack_head(p1.x, p1.y);
        const float4 v3 = unpack_head(p1.z, p1.w);
        a0.x += al.x * v0.x; a0.y += al.x * v0.y; a0.z += al.x * v0.z; a0.w += al.x * v0.w;
        a1.x += al.y * v1.x; a1.y += al.y * v1.y; a1.z += al.y * v1.z; a1.w += al.y * v1.w;
        a2.x += al.z * v2.x; a2.y += al.z * v2.y; a2.z += al.z * v2.z; a2.w += al.z * v2.w;
        a3.x += al.w * v3.x; a3.y += al.w * v3.y; a3.z += al.w * v3.z; a3.w += al.w * v3.w;
    }

    const float4 b4 = *reinterpret_cast<const float4*>(bias + 4 * lane);
    float4 o;
    o.x = fmaxf(0.25f * (a0.x + a1.x + a2.x + a3.x) + b4.x, 0.f);
    o.y = fmaxf(0.25f * (a0.y + a1.y + a2.y + a3.y) + b4.y, 0.f);
    o.z = fmaxf(0.25f * (a0.z + a1.z + a2.z + a3.z) + b4.z, 0.f);
    o.w = fmaxf(0.25f * (a0.w + a1.w + a2.w + a3.w) + b4.w, 0.f);
    if (round_out) {   // h1 feeds GEMM-L2 as A: keep on tf32 grid
        o.x = rnd_tf32(o.x); o.y = rnd_tf32(o.y);
        o.z = rnd_tf32(o.z); o.w = rnd_tf32(o.w);
    }
    *reinterpret_cast<float4*>(out + (long)n * DH + 4 * lane) = o;
}

// ---------------- launch ------------------------------------------------------
extern "C" void kernel_launch(void* const* d_in, const int* in_sizes, int n_in,
                              void* d_out, int out_size) {
    const float* x     = (const float*)d_in[0];
    const int*   eidx  = (const int*)d_in[1];
    const int*   etype = (const int*)d_in[2];
    const float* w1    = (const float*)d_in[3];
    const float* b1    = (const float*)d_in[4];
    const float* w2    = (const float*)d_in[5];
    const float* b2    = (const float*)d_in[6];
    const float* rel   = (const float*)d_in[7];
    const float* lin1  = (const float*)d_in[8];
    const float* line1 = (const float*)d_in[9];
    const float* atts1 = (const float*)d_in[10];
    const float* attd1 = (const float*)d_in[11];
    const float* atte1 = (const float*)d_in[12];
    const float* bias1 = (const float*)d_in[13];
    const float* lin2  = (const float*)d_in[14];
    const float* line2 = (const float*)d_in[15];
    const float* atts2 = (const float*)d_in[16];
    const float* attd2 = (const float*)d_in[17];
    const float* atte2 = (const float*)d_in[18];
    const float* bias2 = (const float*)d_in[19];

    const int N = out_size / DH;          // 20000
    const int E = in_sizes[1] / 2;        // 320000
    const int F = in_sizes[3] / 256;      // 518
    const int* src = eidx;
    const int* dst = eidx + E;

    float *wr, *hidden, *h0, *h1, *as_, *ad_, *relproj;
    __half* hlinh;
    int *cnt, *cursor, *rowptr;
    int2* cedge;
    cudaGetSymbolAddress((void**)&wr, g_wr);
    cudaGetSymbolAddress((void**)&hidden, g_hidden);
    cudaGetSymbolAddress((void**)&h0, g_h0);
    cudaGetSymbolAddress((void**)&h1, g_h1);
    cudaGetSymbolAddress((void**)&hlinh, g_hlinh);
    cudaGetSymbolAddress((void**)&as_, g_as);
    cudaGetSymbolAddress((void**)&ad_, g_ad);
    cudaGetSymbolAddress((void**)&cnt, g_cnt);
    cudaGetSymbolAddress((void**)&cursor, g_cursor);
    cudaGetSymbolAddress((void**)&rowptr, g_rowptr);
    cudaGetSymbolAddress((void**)&cedge, g_cedge);
    cudaGetSymbolAddress((void**)&relproj, g_relproj);

    const long nw1 = (long)F * 256;
    const long nw2 = 256 * DH;
    const long nl  = DH * HD;
    float* w1r = wr;
    float* w2r = wr + nw1;
    float* l1r = wr + nw1 + nw2;
    float* l2r = wr + nw1 + nw2 + nl;

    const int MB = (N + 127) / 128;
    const int AGG_B = (N + 7) / 8;

    // 1: hist + tf32 RNA-rounding of GEMM B matrices (tiny, fused)
    hist_round_kernel<<<(E + 255) / 256, 256>>>(dst, E, cnt,
                                                w1, nw1, w2, nw2, lin1, nl, lin2, wr);
    // 2-3: CSR build
    scan_kernel<<<1, 1024>>>(cnt, rowptr, cursor, N);
    scatter_kernel<<<(E + 255) / 256, 256>>>(src, dst, etype, E, cursor, cedge);

    // 4: encoder GEMM 1 (captured by ncu slot); A = raw x (HW tf32 truncation)
    {
        dim3 g(256 / 128, MB);
        mma_gemm<true, true, false><<<g, 256>>>(N, 256, F, x, w1r, b1, hidden,
                                                nullptr, nullptr, nullptr, nullptr, nullptr);
    }
    // 5: encoder GEMM 2
    {
        dim3 g(1, MB);
        mma_gemm<false, true, false><<<g, 256>>>(N, DH, 256, hidden, w2r, b2, h0,
                                                 nullptr, nullptr, nullptr, nullptr, nullptr);
    }

    // 6: collapsed edge-attention tables (both layers, one launch)
    relproj_kernel<<<2, 128>>>(rel, line1, atte1, line2, atte2, relproj);

    // 7-8: GAT layer 1
    {
        dim3 g(HD / 128, MB);
        mma_gemm<false, false, true><<<g, 256>>>(N, HD, DH, h0, l1r, nullptr, nullptr,
                                                 hlinh, atts1, attd1, as_, ad_);
    }
    gat_agg_kernel<<<AGG_B, 256>>>(hlinh, as_, ad_, rowptr, cedge,
                                   relproj, bias1, h1, N, 1);

    // 9-10: GAT layer 2
    {
        dim3 g(HD / 128, MB);
        mma_gemm<false, false, true><<<g, 256>>>(N, HD, DH, h1, l2r, nullptr, nullptr,
                                                 hlinh, atts2, attd2, as_, ad_);
    }
    gat_agg_kernel<<<AGG_B, 256>>>(hlinh, as_, ad_, rowptr, cedge,
                                   relproj + 26 * HEADS, bias2, (float*)d_out, N, 0);
}

// round 14
// speedup vs baseline: 1.1337x; 1.0434x over previous
#include <cuda_runtime.h>
#include <cuda_fp16.h>
#include <cstdint>

// ---------------- problem-size bounds (fixed by the dataset) ----------------
#define NMAX 20000
#define EMAX 320000
#define FIN  518
#define DH   128     // node embedding dim
#define HEADS 4
#define HD   512     // HEADS * DH
#define CAP  128     // cached edges per node (overflow recomputed)

// ---------------- device scratch (no allocations allowed) -------------------
__device__ float  g_wr[FIN * 256 + 256 * DH + 2 * DH * HD];  // RNA-rounded weights
__device__ float  g_hidden[NMAX * 256];   // encoder hidden (tf32 grid)
__device__ float  g_h0[NMAX * DH];        // encoder out (tf32 grid)
__device__ float  g_h1[NMAX * DH];        // layer1 out (tf32 grid)
__device__ __half g_hlinh[NMAX * HD];     // h @ lin in fp16, layout [n][L][head][4]
__device__ float  g_as[NMAX * HEADS];
__device__ float  g_ad[NMAX * HEADS];
__device__ int    g_cnt[NMAX];            // zero at load; re-zeroed by scan each call
__device__ int    g_cursor[NMAX];         // scatter cursors (scan initializes)
__device__ int    g_rowptr[NMAX + 1];
__device__ int2   g_cedge[EMAX];               // packed {src, type} per CSR slot
__device__ float  g_relproj[2 * 26 * HEADS];   // [layer][26][4]

__device__ __forceinline__ uint32_t f2tf32(float f) {
    uint32_t u;
    asm("cvt.rna.tf32.f32 %0, %1;" : "=r"(u) : "f"(f));
    return u;
}
__device__ __forceinline__ float rnd_tf32(float f) {
    return __uint_as_float(f2tf32(f));
}

// ---------------- hist + weight tf32 rounding (fused; weights are tiny) ------
__global__ void hist_round_kernel(const int* __restrict__ dst, int E,
                                  int* __restrict__ cnt,
                                  const float* __restrict__ w1, long nw1,
                                  const float* __restrict__ w2, long nw2,
                                  const float* __restrict__ l1, long nl,
                                  const float* __restrict__ l2,
                                  float* __restrict__ wr) {
    long gid = blockIdx.x * (long)blockDim.x + threadIdx.x;
    if (gid < E) atomicAdd(&cnt[dst[gid]], 1);
    const long stride = (long)gridDim.x * blockDim.x;
    const long total = nw1 + nw2 + 2 * nl;
    for (long j = gid; j < total; j += stride) {
        long i = j;
        if (i < nw1)      { wr[i] = rnd_tf32(w1[i]); continue; }
        i -= nw1;
        if (i < nw2)      { wr[nw1 + i] = rnd_tf32(w2[i]); continue; }
        i -= nw2;
        if (i < nl)       { wr[nw1 + nw2 + i] = rnd_tf32(l1[i]); continue; }
        i -= nl;
        wr[nw1 + nw2 + nl + i] = rnd_tf32(l2[i]);
    }
}

// single-block exclusive scan of cnt[0..n) -> rowptr[0..n] and cursor[0..n).
// Also zeroes cnt (so the next invocation's hist starts from zero).
__global__ void scan_kernel(int* __restrict__ cnt, int* __restrict__ rowptr,
                            int* __restrict__ cursor, int n) {
    __shared__ int part[1024];
    int tid = threadIdx.x;
    int chunk = (n + 1023) / 1024;
    int b = tid * chunk;
    int e = min(b + chunk, n);
    int s = 0;
    for (int i = b; i < e; i++) { s += cnt[i]; }
    part[tid] = s;
    __syncthreads();
    for (int off = 1; off < 1024; off <<= 1) {
        int v = (tid >= off) ? part[tid - off] : 0;
        __syncthreads();
        part[tid] += v;
        __syncthreads();
    }
    int run = (tid == 0) ? 0 : part[tid - 1];
    for (int i = b; i < e; i++) {
        rowptr[i] = run;
        cursor[i] = run;
        run += cnt[i];
        cnt[i] = 0;                      // reset for next call
    }
    if (tid == 0) rowptr[n] = part[1023];
}

__global__ void scatter_kernel(const int* __restrict__ src, const int* __restrict__ dst,
                               const int* __restrict__ type, int E,
                               int* __restrict__ cursor, int2* __restrict__ cedge) {
    int i = blockIdx.x * blockDim.x + threadIdx.x;
    if (i < E) {
        int p = atomicAdd(&cursor[dst[i]], 1);
        cedge[p] = make_int2(src[i], type[i]);
    }
}

// relproj[layer][r][h]; grid = 2 blocks (one per layer)
__global__ void relproj_kernel(const float* __restrict__ rel_emb,
                               const float* __restrict__ line1,
                               const float* __restrict__ atte1,
                               const float* __restrict__ line2,
                               const float* __restrict__ atte2,
                               float* __restrict__ relproj) {
    const float* line = blockIdx.x ? line2 : line1;
    const float* atte = blockIdx.x ? atte2 : atte1;
    float* rp = relproj + blockIdx.x * 26 * HEADS;
    __shared__ float we[32 * HEADS];
    int tid = threadIdx.x;   // 128 threads
    {
        int k = tid >> 2, h = tid & 3;
        float s = 0.f;
        const float* lp = line + k * HD + h * DH;
        const float* ap = atte + h * DH;
        for (int d = 0; d < DH; d++) s += lp[d] * ap[d];
        we[k * HEADS + h] = s;
    }
    __syncthreads();
    if (tid < 26 * HEADS) {
        int r = tid >> 2, h = tid & 3;
        float s = 0.f;
        for (int k = 0; k < 32; k++) s += rel_emb[r * 32 + k] * we[k * HEADS + h];
        rp[tid] = s;
    }
}

// ---------------- tf32 tensor-core GEMM (cp.async + vector fragments) --------
__device__ __forceinline__ void mma_tf32s(float c[4],
        uint32_t a0, uint32_t a1, uint32_t a2, uint32_t a3,
        uint32_t b0, uint32_t b1) {
    asm volatile(
        "mma.sync.aligned.m16n8k8.row.col.f32.tf32.tf32.f32 "
        "{%0,%1,%2,%3}, {%4,%5,%6,%7}, {%8,%9}, {%0,%1,%2,%3};"
        : "+f"(c[0]), "+f"(c[1]), "+f"(c[2]), "+f"(c[3])
        : "r"(a0), "r"(a1), "r"(a2), "r"(a3), "r"(b0), "r"(b1));
}

__device__ __forceinline__ void cp4(uint32_t smem_u32, const float* gptr, bool pred) {
    int sz = pred ? 4 : 0;
    asm volatile("cp.async.ca.shared.global [%0], [%1], 4, %2;"
                 :: "r"(smem_u32), "l"(gptr), "r"(sz));
}
__device__ __forceinline__ void cp_commit() {
    asm volatile("cp.async.commit_group;");
}
template <int N>
__device__ __forceinline__ void cp_wait() {
    asm volatile("cp.async.wait_group %0;" :: "n"(N));
}

// C = act(A[M,K] @ B[K,N] + bias). BM=128 BN=128 BK=16, 8 warps (2m x 4n).
// Fragment-friendly smem layouts (k-permuted): inner loop = 12 LDS.128 + 32 MMA.
//   A: As[r*16 + permA(c)], permA(c) = ((c&3)<<2)|((c>>2)&1)|(((c>>3)&1)<<1)
//   B: Bs[(k&3)*520 + c*4 + (k>>2)]
// Issue path: loop-invariant per-thread roles, precomputed smem offsets,
// rolling global pointers, minimal per-tile predicates. All cp.async use the
// proven 3-operand zfill form.
// !ATT epilogue stores tf32-RNA-rounded fp32. ATT: fp16 hlinh + fused att dots.
template <bool RELU, bool HAS_BIAS, bool ATT>
__global__ __launch_bounds__(256, 2) void mma_gemm(
        int M, int N, int K,
        const float* __restrict__ A, const float* __restrict__ B,
        const float* __restrict__ bias, float* __restrict__ C,
        __half* __restrict__ Ch,
        const float* __restrict__ atts, const float* __restrict__ attd,
        float* __restrict__ as_, float* __restrict__ ad_) {
    constexpr int BM = 128, BN = 128, BK = 16;
    constexpr int APW = 16;     // A words per row (permuted k)
    constexpr int BPW = 520;    // B words per (k&3) group (pitch 520 = 8 mod 32)
    __shared__ uint32_t As[2][BM * APW];
    __shared__ uint32_t Bs[2][4 * BPW];
    __shared__ float s_att[BM * 2];      // ATT reduction (1KB)

    const int tid  = threadIdx.x;
    const int lane = tid & 31;
    const int warp = tid >> 5;
    const int warpM = warp >> 2;
    const int warpN = warp & 3;
    const int bm = blockIdx.y * BM;
    const int bn = blockIdx.x * BN;
    const int mBase = warpM * 64;
    const int nBase = warpN * 32;
    const int qr = lane >> 2;
    const int qc = lane & 3;

    const uint32_t sA0 = (uint32_t)__cvta_generic_to_shared(&As[0][0]);
    const uint32_t sA1 = (uint32_t)__cvta_generic_to_shared(&As[1][0]);
    const uint32_t sB0 = (uint32_t)__cvta_generic_to_shared(&Bs[0][0]);
    const uint32_t sB1 = (uint32_t)__cvta_generic_to_shared(&Bs[1][0]);

    // ---- loop-invariant load roles ----
    const int ar = tid >> 4, ac = tid & 15;           // A: row base, fixed col
    const int aperm = ((ac & 3) << 2) | ((ac >> 2) & 1) | (((ac >> 3) & 1) << 1);
    const int br = tid >> 7, bc = tid & 127;          // B: row base (0/1), fixed col
    const uint32_t aSmB = (uint32_t)((ar * APW + aperm) * 4);
    uint32_t bSm[8];
#pragma unroll
    for (int i = 0; i < 8; i++) {
        int r = br + 2 * i;
        bSm[i] = (uint32_t)(((r & 3) * BPW + bc * 4 + (r >> 2)) * 4);
    }
    const long aStep = 16L * K;          // A row stride per i (elements)
    const long bStep = 2L * N;           // B row stride per i (elements)
    const float* aNext = A + (long)(bm + ar) * K + ac;
    const float* bNext = B + (long)br * N + bn + bc;
    const int mA = M - bm - ar;          // rows available for this thread's A role
    int kt = 0;

    float acc[4][4][4] = {};

    auto issue = [&](int s) {
        const uint32_t aBase = (s ? sA1 : sA0) + aSmB;
        const uint32_t bBase = s ? sB1 : sB0;
        const bool pA = (kt + ac) < K;
#pragma unroll
        for (int i = 0; i < 8; i++)
            cp4(aBase + (uint32_t)(i * 16 * APW * 4), aNext + i * aStep,
                (16 * i < mA) && pA);
        const int kB = K - kt - br;
#pragma unroll
        for (int i = 0; i < 8; i++)
            cp4(bBase + bSm[i], bNext + i * bStep, (2 * i) < kB);
        cp_commit();
        aNext += BK;
        bNext += (long)BK * N;
        kt += BK;
    };

    const int nkt = (K + BK - 1) / BK;
    issue(0);
    if (nkt > 1) issue(1);

    int s = 0;
    for (int it = 0; it < nkt; it++, s ^= 1) {
        if (it + 1 < nkt) cp_wait<1>(); else cp_wait<0>();
        __syncthreads();

        const uint32_t* Acur = As[s];
        const uint32_t* Bcur = Bs[s];
        uint4 aLo[4], aHi[4], bF[4];
#pragma unroll
        for (int am = 0; am < 4; am++) {
            int r0 = mBase + am * 16 + qr;
            aLo[am] = *reinterpret_cast<const uint4*>(Acur + r0 * APW + qc * 4);
            aHi[am] = *reinterpret_cast<const uint4*>(Acur + (r0 + 8) * APW + qc * 4);
        }
#pragma unroll
        for (int bnn = 0; bnn < 4; bnn++) {
            int c0 = nBase + bnn * 8 + qr;
            bF[bnn] = *reinterpret_cast<const uint4*>(Bcur + qc * BPW + c0 * 4);
        }
#pragma unroll
        for (int am = 0; am < 4; am++)
#pragma unroll
            for (int bnn = 0; bnn < 4; bnn++)
                mma_tf32s(acc[am][bnn], aLo[am].x, aHi[am].x, aLo[am].y, aHi[am].y,
                          bF[bnn].x, bF[bnn].y);
#pragma unroll
        for (int am = 0; am < 4; am++)
#pragma unroll
            for (int bnn = 0; bnn < 4; bnn++)
                mma_tf32s(acc[am][bnn], aLo[am].z, aHi[am].z, aLo[am].w, aHi[am].w,
                          bF[bnn].z, bF[bnn].w);
        __syncthreads();
        if (it + 2 < nkt) issue(s);
    }

    // ---- epilogue ----
    if (!ATT) {
#pragma unroll
        for (int am = 0; am < 4; am++) {
            int r0 = bm + mBase + am * 16 + qr;
#pragma unroll
            for (int bnn = 0; bnn < 4; bnn++) {
                int c0 = bn + nBase + bnn * 8 + 2 * qc;
                float b0 = 0.f, b1 = 0.f;
                if (HAS_BIAS) { b0 = bias[c0]; b1 = bias[c0 + 1]; }
#pragma unroll
                for (int half = 0; half < 2; half++) {
                    int gr = r0 + half * 8;
                    if (gr >= M) continue;
                    float v0 = acc[am][bnn][half * 2 + 0] + b0;
                    float v1 = acc[am][bnn][half * 2 + 1] + b1;
                    if (RELU) { v0 = fmaxf(v0, 0.f); v1 = fmaxf(v1, 0.f); }
                    // outputs feed later GEMMs as A: keep them on the tf32 grid
                    v0 = rnd_tf32(v0); v1 = rnd_tf32(v1);
                    *reinterpret_cast<float2*>(&C[(long)gr * N + c0]) = make_float2(v0, v1);
                }
            }
        }
    } else {
        const int hh = blockIdx.x;                   // head (BN==DH==128)
        // fp16 store in agg layout: halves index = row*HD + L*16 + hh*4 + d
#pragma unroll
        for (int am = 0; am < 4; am++) {
            int r0 = bm + mBase + am * 16 + qr;
#pragma unroll
            for (int bnn = 0; bnn < 4; bnn++) {
                int cl = nBase + bnn * 8 + 2 * qc;   // head-local col (even)
                int L = cl >> 2, d = cl & 3;         // d in {0,2}
#pragma unroll
                for (int half = 0; half < 2; half++) {
                    int gr = r0 + half * 8;
                    if (gr >= M) continue;
                    float v0 = acc[am][bnn][half * 2 + 0];
                    float v1 = acc[am][bnn][half * 2 + 1];
                    __half2 hv = __floats2half2_rn(v0, v1);
                    *reinterpret_cast<__half2*>(
                        Ch + (long)gr * HD + L * 16 + hh * 4 + d) = hv;
                }
            }
        }
        // fused attention dots
        float w0s[4], w1s[4], w0d[4], w1d[4];
#pragma unroll
        for (int bnn = 0; bnn < 4; bnn++) {
            int cl = nBase + bnn * 8 + 2 * qc;
            w0s[bnn] = atts[hh * DH + cl];  w1s[bnn] = atts[hh * DH + cl + 1];
            w0d[bnn] = attd[hh * DH + cl];  w1d[bnn] = attd[hh * DH + cl + 1];
        }
        float ps[4][2], pd[4][2];
#pragma unroll
        for (int am = 0; am < 4; am++)
#pragma unroll
            for (int half = 0; half < 2; half++) {
                float s_ = 0.f, d_ = 0.f;
#pragma unroll
                for (int bnn = 0; bnn < 4; bnn++) {
                    float v0 = acc[am][bnn][half * 2 + 0];
                    float v1 = acc[am][bnn][half * 2 + 1];
                    s_ += v0 * w0s[bnn] + v1 * w1s[bnn];
                    d_ += v0 * w0d[bnn] + v1 * w1d[bnn];
                }
                ps[am][half] = s_; pd[am][half] = d_;
            }
#pragma unroll
        for (int off = 1; off <= 2; off <<= 1)
#pragma unroll
            for (int am = 0; am < 4; am++)
#pragma unroll
                for (int half = 0; half < 2; half++) {
                    ps[am][half] += __shfl_xor_sync(~0u, ps[am][half], off);
                    pd[am][half] += __shfl_xor_sync(~0u, pd[am][half], off);
                }
        s_att[tid] = 0.f;
        if (tid < BM * 2 - 256) s_att[256 + tid] = 0.f;
        __syncthreads();
        if (qc == 0) {
#pragma unroll
            for (int am = 0; am < 4; am++)
#pragma unroll
                for (int half = 0; half < 2; half++) {
                    int lr = mBase + am * 16 + qr + half * 8;   // 0..127
                    atomicAdd(&s_att[lr * 2 + 0], ps[am][half]);
                    atomicAdd(&s_att[lr * 2 + 1], pd[am][half]);
                }
        }
        __syncthreads();
        {
            int lr = tid >> 1, comp = tid & 1;
            int gr = bm + lr;
            if (gr < M) {
                float v = s_att[lr * 2 + comp];
                if (comp) ad_[gr * HEADS + hh] = v;
                else      as_[gr * HEADS + hh] = v;
            }
        }
    }
}

// ---------------- GAT aggregation: one WARP per destination node -------------
__device__ __forceinline__ float leaky02(float x) {
    return (x > 0.f) ? x : 0.2f * x;
}

__device__ __forceinline__ float4 unpack_head(uint32_t lo, uint32_t hi) {
    float2 a = __half22float2(*reinterpret_cast<const __half2*>(&lo));
    float2 b = __half22float2(*reinterpret_cast<const __half2*>(&hi));
    return make_float4(a.x, a.y, b.x, b.y);
}

__global__ __launch_bounds__(256) void gat_agg_kernel(
        const __half* __restrict__ hlinh,
        const float* __restrict__ a_s,
        const float* __restrict__ a_d,
        const int* __restrict__ rowptr,
        const int2* __restrict__ cedge,
        const float* __restrict__ relproj,
        const float* __restrict__ bias,
        float* __restrict__ out, int N, int round_out) {
    const int w    = threadIdx.x >> 5;     // warp in block (8)
    const int lane = threadIdx.x & 31;
    const int n    = blockIdx.x * 8 + w;

    __shared__ __align__(16) float s_rp[32 * HEADS];   // relproj table (26 used)
    __shared__ __align__(16) float s_l[8][CAP][HEADS]; // logits -> alphas (16KB)
    __shared__ int s_src[8][CAP];                      // cached src ids (4KB)

    if (threadIdx.x < 26 * HEADS) s_rp[threadIdx.x] = relproj[threadIdx.x];
    __syncthreads();
    if (n >= N) return;

    const int beg = rowptr[n], end = rowptr[n + 1];
    const int deg = end - beg;

    const float4 ad4 = *reinterpret_cast<const float4*>(a_d + n * HEADS);

    // ---- phase A: logits for all incoming edges (lanes parallel) ----
    float m0 = -1e30f, m1 = -1e30f, m2 = -1e30f, m3 = -1e30f;
    float s0 = 0.f, s1 = 0.f, s2 = 0.f, s3 = 0.f;
    float r0 = 0.f, r1 = 0.f, r2 = 0.f, r3 = 0.f;
    for (int j = lane; j < deg; j += 32) {
        const int2 st = cedge[beg + j];
        const int sp = st.x;
        const int tp = st.y;
        const float4 as4 = *reinterpret_cast<const float4*>(a_s + sp * HEADS);
        const float4 rp4 = *reinterpret_cast<const float4*>(s_rp + tp * HEADS);
        float l0 = leaky02(as4.x + ad4.x + rp4.x);
        float l1 = leaky02(as4.y + ad4.y + rp4.y);
        float l2 = leaky02(as4.z + ad4.z + rp4.z);
        float l3 = leaky02(as4.w + ad4.w + rp4.w);
        r0 += rp4.x; r1 += rp4.y; r2 += rp4.z; r3 += rp4.w;
        if (j < CAP) {
            s_src[w][j] = sp;
            *reinterpret_cast<float4*>(s_l[w][j]) = make_float4(l0, l1, l2, l3);
        }
        if (l0 > m0) { s0 = s0 * __expf(m0 - l0) + 1.f; m0 = l0; } else s0 += __expf(l0 - m0);
        if (l1 > m1) { s1 = s1 * __expf(m1 - l1) + 1.f; m1 = l1; } else s1 += __expf(l1 - m1);
        if (l2 > m2) { s2 = s2 * __expf(m2 - l2) + 1.f; m2 = l2; } else s2 += __expf(l2 - m2);
        if (l3 > m3) { s3 = s3 * __expf(m3 - l3) + 1.f; m3 = l3; } else s3 += __expf(l3 - m3);
    }
#pragma unroll
    for (int off = 16; off > 0; off >>= 1) {
        float mo, so;
        mo = __shfl_xor_sync(~0u, m0, off); so = __shfl_xor_sync(~0u, s0, off);
        if (mo > m0) { s0 = s0 * __expf(m0 - mo) + so; m0 = mo; } else s0 += so * __expf(mo - m0);
        mo = __shfl_xor_sync(~0u, m1, off); so = __shfl_xor_sync(~0u, s1, off);
        if (mo > m1) { s1 = s1 * __expf(m1 - mo) + so; m1 = mo; } else s1 += so * __expf(mo - m1);
        mo = __shfl_xor_sync(~0u, m2, off); so = __shfl_xor_sync(~0u, s2, off);
        if (mo > m2) { s2 = s2 * __expf(m2 - mo) + so; m2 = mo; } else s2 += so * __expf(mo - m2);
        mo = __shfl_xor_sync(~0u, m3, off); so = __shfl_xor_sync(~0u, s3, off);
        if (mo > m3) { s3 = s3 * __expf(m3 - mo) + so; m3 = mo; } else s3 += so * __expf(mo - m3);
        r0 += __shfl_xor_sync(~0u, r0, off);
        r1 += __shfl_xor_sync(~0u, r1, off);
        r2 += __shfl_xor_sync(~0u, r2, off);
        r3 += __shfl_xor_sync(~0u, r3, off);
    }

    // self loop: a_e = mean of relproj over incoming edges
    const float4 asn = *reinterpret_cast<const float4*>(a_s + n * HEADS);
    const float dinv = 1.f / (float)max(deg, 1);
    float ls0 = leaky02(asn.x + ad4.x + r0 * dinv);
    float ls1 = leaky02(asn.y + ad4.y + r1 * dinv);
    float ls2 = leaky02(asn.z + ad4.z + r2 * dinv);
    float ls3 = leaky02(asn.w + ad4.w + r3 * dinv);
    if (ls0 > m0) { s0 = s0 * __expf(m0 - ls0) + 1.f; m0 = ls0; } else s0 += __expf(ls0 - m0);
    if (ls1 > m1) { s1 = s1 * __expf(m1 - ls1) + 1.f; m1 = ls1; } else s1 += __expf(ls1 - m1);
    if (ls2 > m2) { s2 = s2 * __expf(m2 - ls2) + 1.f; m2 = ls2; } else s2 += __expf(ls2 - m2);
    if (ls3 > m3) { s3 = s3 * __expf(m3 - ls3) + 1.f; m3 = ls3; } else s3 += __expf(ls3 - m3);
    const float i0 = 1.f / (s0 + 1e-16f), i1 = 1.f / (s1 + 1e-16f);
    const float i2 = 1.f / (s2 + 1e-16f), i3 = 1.f / (s3 + 1e-16f);
    const float la0 = __expf(ls0 - m0) * i0, la1 = __expf(ls1 - m1) * i1;
    const float la2 = __expf(ls2 - m2) * i2, la3 = __expf(ls3 - m3) * i3;

    __syncwarp();
    const int ncached = min(deg, CAP);
    for (int j = lane; j < ncached; j += 32) {
        float4 l4 = *reinterpret_cast<float4*>(s_l[w][j]);
        l4.x = __expf(l4.x - m0) * i0;
        l4.y = __expf(l4.y - m1) * i1;
        l4.z = __expf(l4.z - m2) * i2;
        l4.w = __expf(l4.w - m3) * i3;
        *reinterpret_cast<float4*>(s_l[w][j]) = l4;
    }
    __syncwarp();

    // ---- phase B: lane L owns dims [4L,4L+4) per head; 2 x LDG.128 per edge.
    float4 a0, a1, a2, a3;
    {
        const uint4* hp = reinterpret_cast<const uint4*>(hlinh + (long)n * HD) + lane * 2;
        const uint4 p0 = hp[0], p1 = hp[1];
        float4 v0 = unpack_head(p0.x, p0.y);
        float4 v1 = unpack_head(p0.z, p0.w);
        float4 v2 = unpack_head(p1.x, p1.y);
        float4 v3 = unpack_head(p1.z, p1.w);
        a0 = make_float4(la0 * v0.x, la0 * v0.y, la0 * v0.z, la0 * v0.w);
        a1 = make_float4(la1 * v1.x, la1 * v1.y, la1 * v1.z, la1 * v1.w);
        a2 = make_float4(la2 * v2.x, la2 * v2.y, la2 * v2.z, la2 * v2.w);
        a3 = make_float4(la3 * v3.x, la3 * v3.y, la3 * v3.z, la3 * v3.w);
    }
#pragma unroll 4
    for (int j = 0; j < ncached; j++) {
        const int sp = s_src[w][j];
        const float4 al = *reinterpret_cast<const float4*>(s_l[w][j]);
        const uint4* hp = reinterpret_cast<const uint4*>(hlinh + (long)sp * HD) + lane * 2;
        const uint4 p0 = hp[0], p1 = hp[1];
        const float4 v0 = unpack_head(p0.x, p0.y);
        const float4 v1 = unpack_head(p0.z, p0.w);
        const float4 v2 = unpack_head(p1.x, p1.y);
        const float4 v3 = unpack_head(p1.z, p1.w);
        a0.x += al.x * v0.x; a0.y += al.x * v0.y; a0.z += al.x * v0.z; a0.w += al.x * v0.w;
        a1.x += al.y * v1.x; a1.y += al.y * v1.y; a1.z += al.y * v1.z; a1.w += al.y * v1.w;
        a2.x += al.z * v2.x; a2.y += al.z * v2.y; a2.z += al.z * v2.z; a2.w += al.z * v2.w;
        a3.x += al.w * v3.x; a3.y += al.w * v3.y; a3.z += al.w * v3.z; a3.w += al.w * v3.w;
    }
    // overflow tail (deg > CAP): recompute alphas
    for (int j = CAP; j < deg; j++) {
        const int2 st = cedge[beg + j];
        const int sp = st.x;
        const float4 as4 = *reinterpret_cast<const float4*>(a_s + sp * HEADS);
        const float4 rp4 = *reinterpret_cast<const float4*>(s_rp + st.y * HEADS);
        float4 al;
        al.x = __expf(leaky02(as4.x + ad4.x + rp4.x) - m0) * i0;
        al.y = __expf(leaky02(as4.y + ad4.y + rp4.y) - m1) * i1;
        al.z = __expf(leaky02(as4.z + ad4.z + rp4.z) - m2) * i2;
        al.w = __expf(leaky02(as4.w + ad4.w + rp4.w) - m3) * i3;
        const uint4* hp = reinterpret_cast<const uint4*>(hlinh + (long)sp * HD) + lane * 2;
        const uint4 p0 = hp[0], p1 = hp[1];
        const float4 v0 = unpack_head(p0.x, p0.y);
        const float4 v1 = unpack_head(p0.z, p0.w);
        const float4 v2 = unpack_head(p1.x, p1.y);
        const float4 v3 = unpack_head(p1.z, p1.w);
        a0.x += al.x * v0.x; a0.y += al.x * v0.y; a0.z += al.x * v0.z; a0.w += al.x * v0.w;
        a1.x += al.y * v1.x; a1.y += al.y * v1.y; a1.z += al.y * v1.z; a1.w += al.y * v1.w;
        a2.x += al.z * v2.x; a2.y += al.z * v2.y; a2.z += al.z * v2.z; a2.w += al.z * v2.w;
        a3.x += al.w * v3.x; a3.y += al.w * v3.y; a3.z += al.w * v3.z; a3.w += al.w * v3.w;
    }

    const float4 b4 = *reinterpret_cast<const float4*>(bias + 4 * lane);
    float4 o;
    o.x = fmaxf(0.25f * (a0.x + a1.x + a2.x + a3.x) + b4.x, 0.f);
    o.y = fmaxf(0.25f * (a0.y + a1.y + a2.y + a3.y) + b4.y, 0.f);
    o.z = fmaxf(0.25f * (a0.z + a1.z + a2.z + a3.z) + b4.z, 0.f);
    o.w = fmaxf(0.25f * (a0.w + a1.w + a2.w + a3.w) + b4.w, 0.f);
    if (round_out) {   // h1 feeds GEMM-L2 as A: keep on tf32 grid
        o.x = rnd_tf32(o.x); o.y = rnd_tf32(o.y);
        o.z = rnd_tf32(o.z); o.w = rnd_tf32(o.w);
    }
    *reinterpret_cast<float4*>(out + (long)n * DH + 4 * lane) = o;
}

// ---------------- launch ------------------------------------------------------
extern "C" void kernel_launch(void* const* d_in, const int* in_sizes, int n_in,
                              void* d_out, int out_size) {
    const float* x     = (const float*)d_in[0];
    const int*   eidx  = (const int*)d_in[1];
    const int*   etype = (const int*)d_in[2];
    const float* w1    = (const float*)d_in[3];
    const float* b1    = (const float*)d_in[4];
    const float* w2    = (const float*)d_in[5];
    const float* b2    = (const float*)d_in[6];
    const float* rel   = (const float*)d_in[7];
    const float* lin1  = (const float*)d_in[8];
    const float* line1 = (const float*)d_in[9];
    const float* atts1 = (const float*)d_in[10];
    const float* attd1 = (const float*)d_in[11];
    const float* atte1 = (const float*)d_in[12];
    const float* bias1 = (const float*)d_in[13];
    const float* lin2  = (const float*)d_in[14];
    const float* line2 = (const float*)d_in[15];
    const float* atts2 = (const float*)d_in[16];
    const float* attd2 = (const float*)d_in[17];
    const float* atte2 = (const float*)d_in[18];
    const float* bias2 = (const float*)d_in[19];

    const int N = out_size / DH;          // 20000
    const int E = in_sizes[1] / 2;        // 320000
    const int F = in_sizes[3] / 256;      // 518
    const int* src = eidx;
    const int* dst = eidx + E;

    float *wr, *hidden, *h0, *h1, *as_, *ad_, *relproj;
    __half* hlinh;
    int *cnt, *cursor, *rowptr;
    int2* cedge;
    cudaGetSymbolAddress((void**)&wr, g_wr);
    cudaGetSymbolAddress((void**)&hidden, g_hidden);
    cudaGetSymbolAddress((void**)&h0, g_h0);
    cudaGetSymbolAddress((void**)&h1, g_h1);
    cudaGetSymbolAddress((void**)&hlinh, g_hlinh);
    cudaGetSymbolAddress((void**)&as_, g_as);
    cudaGetSymbolAddress((void**)&ad_, g_ad);
    cudaGetSymbolAddress((void**)&cnt, g_cnt);
    cudaGetSymbolAddress((void**)&cursor, g_cursor);
    cudaGetSymbolAddress((void**)&rowptr, g_rowptr);
    cudaGetSymbolAddress((void**)&cedge, g_cedge);
    cudaGetSymbolAddress((void**)&relproj, g_relproj);

    const long nw1 = (long)F * 256;
    const long nw2 = 256 * DH;
    const long nl  = DH * HD;
    float* w1r = wr;
    float* w2r = wr + nw1;
    float* l1r = wr + nw1 + nw2;
    float* l2r = wr + nw1 + nw2 + nl;

    const int MB = (N + 127) / 128;
    const int AGG_B = (N + 7) / 8;

    // 1: hist + tf32 RNA-rounding of GEMM B matrices (tiny, fused)
    hist_round_kernel<<<(E + 255) / 256, 256>>>(dst, E, cnt,
                                                w1, nw1, w2, nw2, lin1, nl, lin2, wr);
    // 2-3: CSR build
    scan_kernel<<<1, 1024>>>(cnt, rowptr, cursor, N);
    scatter_kernel<<<(E + 255) / 256, 256>>>(src, dst, etype, E, cursor, cedge);

    // 4: encoder GEMM 1 (captured by ncu slot); A = raw x (HW tf32 truncation)
    {
        dim3 g(256 / 128, MB);
        mma_gemm<true, true, false><<<g, 256>>>(N, 256, F, x, w1r, b1, hidden,
                                                nullptr, nullptr, nullptr, nullptr, nullptr);
    }
    // 5: encoder GEMM 2
    {
        dim3 g(1, MB);
        mma_gemm<false, true, false><<<g, 256>>>(N, DH, 256, hidden, w2r, b2, h0,
                                                 nullptr, nullptr, nullptr, nullptr, nullptr);
    }

    // 6: collapsed edge-attention tables (both layers, one launch)
    relproj_kernel<<<2, 128>>>(rel, line1, atte1, line2, atte2, relproj);

    // 7-8: GAT layer 1
    {
        dim3 g(HD / 128, MB);
        mma_gemm<false, false, true><<<g, 256>>>(N, HD, DH, h0, l1r, nullptr, nullptr,
                                                 hlinh, atts1, attd1, as_, ad_);
    }
    gat_agg_kernel<<<AGG_B, 256>>>(hlinh, as_, ad_, rowptr, cedge,
                                   relproj, bias1, h1, N, 1);

    // 9-10: GAT layer 2
    {
        dim3 g(HD / 128, MB);
        mma_gemm<false, false, true><<<g, 256>>>(N, HD, DH, h1, l2r, nullptr, nullptr,
                                                 hlinh, atts2, attd2, as_, ad_);
    }
    gat_agg_kernel<<<AGG_B, 256>>>(hlinh, as_, ad_, rowptr, cedge,
                                   relproj + 26 * HEADS, bias2, (float*)d_out, N, 0);
}